// round 6
// baseline (speedup 1.0000x reference)
#include <cuda_runtime.h>
#include <math.h>

#define HD     128
#define NB     32          // batch
#define NQ     32          // q heads
#define NKV    8           // kv heads
#define REP    4           // NQ / NKV
#define DIM    4096
#define TSEQ   2048
#define NCHUNK 4
#define CHLEN  512         // TSEQ / NCHUNK
#define QKV_ROWS (DIM + 2*NKV*HD)   // 6144

// ---------------- scratch (no allocations allowed) ----------------
__device__ float g_xT[DIM*NB];                       // x transposed [k][b]
__device__ float g_qkv[QKV_ROWS*NB];                 // [row][b]: rows 0..4095 q, 4096..5119 k, 5120..6143 v
__device__ float g_pm[NB*NKV*REP*NCHUNK];            // partial max
__device__ float g_pl[NB*NKV*REP*NCHUNK];            // partial sumexp
__device__ float g_pacc[NB*NKV*REP*NCHUNK*HD];       // partial weighted-V
__device__ float g_attT[DIM*NB];                     // attention out transposed [row][b]

// ---------------- transpose x [32][4096] -> xT [4096][32] ----------------
__global__ void k_transpose(const float* __restrict__ x) {
    int i = blockIdx.x * blockDim.x + threadIdx.x;
    if (i < DIM * NB) {
        int b = i / DIM;
        int k = i - b * DIM;
        g_xT[k * NB + b] = x[i];     // coalesced read, scattered write (512KB, cheap)
    }
}

// ---------------- skinny GEMM: out[row][b] = sum_k W[row][k] * x[b][k] ----------------
// lane = batch. Warp owns RPW rows. W tile staged to shared, read as broadcast LDS128.
// SRC: 0 -> g_xT, 1 -> g_attT.  DST: 0 -> g_qkv[(off+row)*NB+lane], 1 -> dOut[lane*DIM+row]
template<int RPW, int SRC, int DST>
__global__ void __launch_bounds__(256) k_gemm(
    const float* __restrict__ W0, const float* __restrict__ W1, int splitRow,
    float* __restrict__ dOut, int outRowOff)
{
    const int ROWS = 8 * RPW;                 // rows per block (8 warps)
    __shared__ float Wsh[8*RPW][128];

    const int tid  = threadIdx.x;
    const int lane = tid & 31;                // = batch index
    const int wid  = tid >> 5;
    const int rowBlk = blockIdx.x * ROWS;

    const float* __restrict__ xT = (SRC == 0) ? g_xT : g_attT;

    float acc[RPW];
#pragma unroll
    for (int r = 0; r < RPW; r++) acc[r] = 0.f;

    for (int k0 = 0; k0 < DIM; k0 += 128) {
        __syncthreads();
        // stage ROWS x 128 floats, coalesced float4
#pragma unroll
        for (int j = 0; j < (ROWS * 128) / (256 * 4); j++) {
            int idx4 = tid + j * 256;
            int lr   = idx4 >> 5;             // local row
            int kk   = (idx4 & 31) << 2;
            int grow = rowBlk + lr;
            const float* Wp = (grow < splitRow)
                ? (W0 + (size_t)grow * DIM)
                : (W1 + (size_t)(grow - splitRow) * DIM);
            *(float4*)&Wsh[lr][kk] = *(const float4*)(Wp + k0 + kk);
        }
        __syncthreads();

        const float* xp = xT + (size_t)k0 * NB + lane;
#pragma unroll 8
        for (int kk = 0; kk < 128; kk += 4) {
            float x0 = xp[(kk + 0) * NB];
            float x1 = xp[(kk + 1) * NB];
            float x2 = xp[(kk + 2) * NB];
            float x3 = xp[(kk + 3) * NB];
#pragma unroll
            for (int r = 0; r < RPW; r++) {
                float4 w4 = *(const float4*)&Wsh[wid * RPW + r][kk];   // broadcast
                acc[r] = fmaf(w4.x, x0, acc[r]);
                acc[r] = fmaf(w4.y, x1, acc[r]);
                acc[r] = fmaf(w4.z, x2, acc[r]);
                acc[r] = fmaf(w4.w, x3, acc[r]);
            }
        }
    }

#pragma unroll
    for (int r = 0; r < RPW; r++) {
        int row = rowBlk + wid * RPW + r;
        if (DST == 0) g_qkv[(size_t)(outRowOff + row) * NB + lane] = acc[r];
        else          dOut[(size_t)lane * DIM + row] = acc[r];
    }
}

// ---------------- RoPE on q (rows 0..4095) and k (rows 4096..5119) ----------------
__global__ void k_rope(const float* __restrict__ fc, const float* __restrict__ fs) {
    int id = blockIdx.x * blockDim.x + threadIdx.x;   // (NQ+NKV)*64*NB = 81920
    if (id >= (NQ + NKV) * 64 * NB) return;
    int b = id & 31;
    int p = id >> 5;            // pair index
    int h = p >> 6;             // head 0..39
    int i = p & 63;             // rotary pair within head
    int baseRow = (h < NQ) ? h * HD : DIM + (h - NQ) * HD;
    int r0 = baseRow + 2 * i;
    float c = fc[i], s = fs[i];
    float t0 = g_qkv[(size_t)r0 * NB + b];
    float t1 = g_qkv[(size_t)(r0 + 1) * NB + b];
    g_qkv[(size_t)r0 * NB + b]       = t0 * c - t1 * s;
    g_qkv[(size_t)(r0 + 1) * NB + b] = t0 * s + t1 * c;
}

// ---------------- split-KV attention: block = (chunk, g, b), 128 threads ----------------
__global__ void __launch_bounds__(128) k_attn(const float* __restrict__ cache_k,
                                              const float* __restrict__ cache_v)
{
    const int c   = blockIdx.x;    // chunk
    const int g   = blockIdx.y;    // kv head
    const int b   = blockIdx.z;    // batch
    const int tid = threadIdx.x, lane = tid & 31, wid = tid >> 5;

    __shared__ float Ssh[REP][CHLEN];      // scores -> exp values
    __shared__ float Red[4][REP][HD];      // cross-warp AV reduce

    const float scale = 0.088388347648318447f;  // 1/sqrt(128)

    // q in registers: lane covers d = lane*4..lane*4+3
    float4 q4[REP];
#pragma unroll
    for (int r = 0; r < REP; r++) {
        int rowBase = (g * REP + r) * HD + lane * 4;
        q4[r].x = g_qkv[(size_t)(rowBase + 0) * NB + b] * scale;
        q4[r].y = g_qkv[(size_t)(rowBase + 1) * NB + b] * scale;
        q4[r].z = g_qkv[(size_t)(rowBase + 2) * NB + b] * scale;
        q4[r].w = g_qkv[(size_t)(rowBase + 3) * NB + b] * scale;
    }

    const size_t strT   = (size_t)NKV * HD;                       // 1024
    const size_t baseBG = (size_t)b * TSEQ * strT + (size_t)g * HD;

    // ---- scores: warp owns t_loc in [wid*128, wid*128+128) ----
    for (int i = 0; i < 128; i++) {
        int tl = wid * 128 + i;
        int t  = c * CHLEN + tl;
        float4 k4;
        if (t == TSEQ - 1) {    // new k (post-RoPE) from scratch, not cache
            int rb = DIM + g * HD + lane * 4;
            k4.x = g_qkv[(size_t)(rb + 0) * NB + b];
            k4.y = g_qkv[(size_t)(rb + 1) * NB + b];
            k4.z = g_qkv[(size_t)(rb + 2) * NB + b];
            k4.w = g_qkv[(size_t)(rb + 3) * NB + b];
        } else {
            k4 = *(const float4*)(cache_k + baseBG + (size_t)t * strT + lane * 4);
        }
        float p0 = fmaf(q4[0].x, k4.x, fmaf(q4[0].y, k4.y, fmaf(q4[0].z, k4.z, q4[0].w * k4.w)));
        float p1 = fmaf(q4[1].x, k4.x, fmaf(q4[1].y, k4.y, fmaf(q4[1].z, k4.z, q4[1].w * k4.w)));
        float p2 = fmaf(q4[2].x, k4.x, fmaf(q4[2].y, k4.y, fmaf(q4[2].z, k4.z, q4[2].w * k4.w)));
        float p3 = fmaf(q4[3].x, k4.x, fmaf(q4[3].y, k4.y, fmaf(q4[3].z, k4.z, q4[3].w * k4.w)));
#pragma unroll
        for (int off = 16; off > 0; off >>= 1) {
            p0 += __shfl_xor_sync(0xffffffffu, p0, off);
            p1 += __shfl_xor_sync(0xffffffffu, p1, off);
            p2 += __shfl_xor_sync(0xffffffffu, p2, off);
            p3 += __shfl_xor_sync(0xffffffffu, p3, off);
        }
        if (lane == 0) { Ssh[0][tl] = p0; Ssh[1][tl] = p1; Ssh[2][tl] = p2; Ssh[3][tl] = p3; }
    }
    __syncthreads();

    // ---- partial softmax: warp wid handles rep r = wid ----
    {
        int r = wid;
        float v[16];
        float m = -1e30f;
#pragma unroll
        for (int j = 0; j < 16; j++) { v[j] = Ssh[r][lane + j * 32]; m = fmaxf(m, v[j]); }
#pragma unroll
        for (int off = 16; off > 0; off >>= 1) m = fmaxf(m, __shfl_xor_sync(0xffffffffu, m, off));
        float l = 0.f;
#pragma unroll
        for (int j = 0; j < 16; j++) { float e = __expf(v[j] - m); l += e; Ssh[r][lane + j * 32] = e; }
#pragma unroll
        for (int off = 16; off > 0; off >>= 1) l += __shfl_xor_sync(0xffffffffu, l, off);
        if (lane == 0) {
            int idx = ((b * NKV + g) * REP + r) * NCHUNK + c;
            g_pm[idx] = m;
            g_pl[idx] = l;
        }
    }
    __syncthreads();

    // ---- AV: warp owns t quarter, lane covers d = lane*4 ----
    float4 a4[REP];
#pragma unroll
    for (int r = 0; r < REP; r++) { a4[r].x = a4[r].y = a4[r].z = a4[r].w = 0.f; }
    for (int i = 0; i < 128; i++) {
        int tl = wid * 128 + i;
        int t  = c * CHLEN + tl;
        float4 v4;
        if (t == TSEQ - 1) {
            int rb = DIM + NKV * HD + g * HD + lane * 4;
            v4.x = g_qkv[(size_t)(rb + 0) * NB + b];
            v4.y = g_qkv[(size_t)(rb + 1) * NB + b];
            v4.z = g_qkv[(size_t)(rb + 2) * NB + b];
            v4.w = g_qkv[(size_t)(rb + 3) * NB + b];
        } else {
            v4 = *(const float4*)(cache_v + baseBG + (size_t)t * strT + lane * 4);
        }
#pragma unroll
        for (int r = 0; r < REP; r++) {
            float p = Ssh[r][tl];            // broadcast
            a4[r].x = fmaf(p, v4.x, a4[r].x);
            a4[r].y = fmaf(p, v4.y, a4[r].y);
            a4[r].z = fmaf(p, v4.z, a4[r].z);
            a4[r].w = fmaf(p, v4.w, a4[r].w);
        }
    }
#pragma unroll
    for (int r = 0; r < REP; r++) *(float4*)&Red[wid][r][lane * 4] = a4[r];
    __syncthreads();
    {
        int r = wid;
        float4 s0 = *(const float4*)&Red[0][r][lane * 4];
        float4 s1 = *(const float4*)&Red[1][r][lane * 4];
        float4 s2 = *(const float4*)&Red[2][r][lane * 4];
        float4 s3 = *(const float4*)&Red[3][r][lane * 4];
        float4 o;
        o.x = s0.x + s1.x + s2.x + s3.x;
        o.y = s0.y + s1.y + s2.y + s3.y;
        o.z = s0.z + s1.z + s2.z + s3.z;
        o.w = s0.w + s1.w + s2.w + s3.w;
        int idx = ((b * NKV + g) * REP + r) * NCHUNK + c;
        *(float4*)&g_pacc[(size_t)idx * HD + lane * 4] = o;
    }
}

// ---------------- combine split-KV partials -> attT [row][b] ----------------
__global__ void __launch_bounds__(128) k_combine() {
    int b  = blockIdx.x;
    int qh = blockIdx.y;
    int g = qh >> 2, r = qh & 3;
    int base = ((b * NKV + g) * REP + r) * NCHUNK;
    float m0 = g_pm[base + 0], m1 = g_pm[base + 1], m2 = g_pm[base + 2], m3 = g_pm[base + 3];
    float M = fmaxf(fmaxf(m0, m1), fmaxf(m2, m3));
    float w0 = __expf(m0 - M), w1 = __expf(m1 - M), w2 = __expf(m2 - M), w3 = __expf(m3 - M);
    float L = g_pl[base + 0] * w0 + g_pl[base + 1] * w1 + g_pl[base + 2] * w2 + g_pl[base + 3] * w3;
    float inv = 1.f / L;
    int d = threadIdx.x;
    float val = w0 * g_pacc[(size_t)(base + 0) * HD + d];
    val = fmaf(w1, g_pacc[(size_t)(base + 1) * HD + d], val);
    val = fmaf(w2, g_pacc[(size_t)(base + 2) * HD + d], val);
    val = fmaf(w3, g_pacc[(size_t)(base + 3) * HD + d], val);
    g_attT[(size_t)(qh * HD + d) * NB + b] = val * inv;
}

// ---------------- launch ----------------
extern "C" void kernel_launch(void* const* d_in, const int* in_sizes, int n_in,
                              void* d_out, int out_size) {
    const float* x  = (const float*)d_in[0];
    const float* wq = (const float*)d_in[1];
    const float* wk = (const float*)d_in[2];
    const float* wv = (const float*)d_in[3];
    const float* wo = (const float*)d_in[4];
    const float* fc = (const float*)d_in[5];
    const float* fs = (const float*)d_in[6];
    const float* ck = (const float*)d_in[7];
    const float* cv = (const float*)d_in[8];
    float* out = (float*)d_out;

    k_transpose<<<(DIM * NB + 255) / 256, 256>>>(x);

    // wq: 4096 rows, 32 rows/block -> 128 blocks
    k_gemm<4, 0, 0><<<128, 256>>>(wq, wq, 1 << 30, nullptr, 0);
    // wk+wv fused: 2048 rows, 16 rows/block -> 128 blocks (rows 0..1023 = wk, 1024..2047 = wv)
    k_gemm<2, 0, 0><<<128, 256>>>(wk, wv, 1024, nullptr, DIM);

    k_rope<<<((NQ + NKV) * 64 * NB + 255) / 256, 256>>>(fc, fs);

    k_attn<<<dim3(NCHUNK, NKV, NB), 128>>>(ck, cv);
    k_combine<<<dim3(NB, NQ), 128>>>();

    // wo: 4096 rows -> 128 blocks, reads g_attT, writes out[b][dim]
    k_gemm<4, 1, 1><<<128, 256>>>(wo, wo, 1 << 30, out, 0);
}

// round 9
// speedup vs baseline: 1.5299x; 1.5299x over previous
#include <cuda_runtime.h>
#include <math.h>

#define HD     128
#define NB     32          // batch
#define NQ     32          // q heads
#define NKV    8           // kv heads
#define REP    4           // NQ / NKV
#define DIM    4096
#define TSEQ   2048
#define NCHUNK 8
#define CHLEN  256         // TSEQ / NCHUNK
#define QKV_ROWS (DIM + 2*NKV*HD)   // 6144

// ---------------- scratch (no allocations allowed) ----------------
__device__ __align__(16) float g_xT[DIM*NB];                 // packed [k>>2][b][4]
__device__ __align__(16) float g_qkv[QKV_ROWS*NB];           // [row][b]
__device__ __align__(16) float g_pm[NB*NKV*REP*NCHUNK];
__device__ __align__(16) float g_pl[NB*NKV*REP*NCHUNK];
__device__ __align__(16) float g_pacc[NB*NKV*REP*NCHUNK*HD];
__device__ __align__(16) float g_attT[DIM*NB];               // packed [row>>2][b][4]

// ---------------- f32x2 helpers (sm_100+) ----------------
typedef unsigned long long ull;
__device__ __forceinline__ ull pk2(float lo, float hi) {
    ull r; asm("mov.b64 %0,{%1,%2};" : "=l"(r) : "f"(lo), "f"(hi)); return r;
}
__device__ __forceinline__ void upk2(float& lo, float& hi, ull v) {
    asm("mov.b64 {%0,%1},%2;" : "=f"(lo), "=f"(hi) : "l"(v));
}
__device__ __forceinline__ void fma2(ull& d, ull a, ull b) {
    asm("fma.rn.f32x2 %0,%1,%2,%0;" : "+l"(d) : "l"(a), "l"(b));
}

// ---------------- transpose x [32][4096] -> xT packed [k/4][b][4] ----------------
__global__ void k_transpose(const float* __restrict__ x) {
    int t = blockIdx.x * blockDim.x + threadIdx.x;   // 32768 threads
    if (t < (DIM / 4) * NB) {
        int b  = t & 31;
        int k4 = t >> 5;
        float4 v = *(const float4*)(x + (size_t)b * DIM + k4 * 4);
        *(float4*)&g_xT[(size_t)k4 * (NB * 4) + b * 4] = v;   // coalesced write
    }
}

// ---------------- skinny GEMM (f32x2) + fused RoPE epilogue ----------------
// lane = batch. Warp owns RPW consecutive rows. W tile staged to shared (broadcast LDS128).
// SRC: 0 -> g_xT, 1 -> g_attT (both packed [k/4][b][4]).
// DST: 0 -> g_qkv[(off+row)*NB+lane], 1 -> dOut[lane*DIM+row]
// Rows < ropeLimit get RoPE applied (pair (2i,2i+1) within one thread's accs).
template<int RPW, int SRC, int DST>
__global__ void __launch_bounds__(256) k_gemm(
    const float* __restrict__ W0, const float* __restrict__ W1, int splitRow,
    float* __restrict__ dOut, int outRowOff, int ropeLimit,
    const float* __restrict__ fc, const float* __restrict__ fs)
{
    const int ROWS = 8 * RPW;
    __shared__ __align__(16) float Wsh[8*RPW][128];

    const int tid  = threadIdx.x;
    const int lane = tid & 31;                 // batch
    const int wid  = tid >> 5;
    const int rowBlk = blockIdx.x * ROWS;

    const float* __restrict__ xT = (SRC == 0) ? g_xT : g_attT;

    ull acc2[RPW];
#pragma unroll
    for (int r = 0; r < RPW; r++) acc2[r] = pk2(0.f, 0.f);

    for (int k0 = 0; k0 < DIM; k0 += 128) {
        __syncthreads();
#pragma unroll
        for (int j = 0; j < (ROWS * 128) / (256 * 4); j++) {
            int idx4 = tid + j * 256;
            int lr   = idx4 >> 5;
            int kk   = (idx4 & 31) << 2;
            int grow = rowBlk + lr;
            const float* Wp = (grow < splitRow)
                ? (W0 + (size_t)grow * DIM)
                : (W1 + (size_t)(grow - splitRow) * DIM);
            *(float4*)&Wsh[lr][kk] = *(const float4*)(Wp + k0 + kk);
        }
        __syncthreads();

#pragma unroll 8
        for (int kk = 0; kk < 128; kk += 4) {
            float4 xv = *(const float4*)(xT + (size_t)((k0 + kk) >> 2) * (NB * 4) + lane * 4);
            ull x01 = pk2(xv.x, xv.y);
            ull x23 = pk2(xv.z, xv.w);
#pragma unroll
            for (int r = 0; r < RPW; r++) {
                float4 w4 = *(const float4*)&Wsh[wid * RPW + r][kk];   // broadcast
                fma2(acc2[r], pk2(w4.x, w4.y), x01);
                fma2(acc2[r], pk2(w4.z, w4.w), x23);
            }
        }
    }

    float accv[RPW];
#pragma unroll
    for (int r = 0; r < RPW; r++) { float lo, hi; upk2(lo, hi, acc2[r]); accv[r] = lo + hi; }

    // fused RoPE on row pairs + store
#pragma unroll
    for (int rp = 0; rp < RPW / 2; rp++) {
        int row0 = rowBlk + wid * RPW + 2 * rp;
        float a0 = accv[2 * rp], a1 = accv[2 * rp + 1];
        if (row0 < ropeLimit) {
            int ii = (row0 & (HD - 1)) >> 1;
            float cc = fc[ii], ss = fs[ii];
            float n0 = a0 * cc - a1 * ss;
            float n1 = a0 * ss + a1 * cc;
            a0 = n0; a1 = n1;
        }
        if (DST == 0) {
            g_qkv[(size_t)(outRowOff + row0)     * NB + lane] = a0;
            g_qkv[(size_t)(outRowOff + row0 + 1) * NB + lane] = a1;
        } else {
            dOut[(size_t)lane * DIM + row0]     = a0;
            dOut[(size_t)lane * DIM + row0 + 1] = a1;
        }
    }
}

// ---------------- split-KV attention: block = (chunk, g, b), 128 threads ----------------
// Scores: lane = (tq = lane&3 token-in-quad, dg = lane>>2 d-group of 16 floats).
// Warp handles 64 tokens = 16 quad-iterations, branch-free (new token via tail).
__global__ void __launch_bounds__(128) k_attn(const float* __restrict__ cache_k,
                                              const float* __restrict__ cache_v,
                                              int c0)
{
    const int c   = c0 + blockIdx.x;
    const int g   = blockIdx.y;
    const int b   = blockIdx.z;
    const int tid = threadIdx.x, lane = tid & 31, wid = tid >> 5;
    const int tq  = lane & 3, dg = lane >> 2;

    __shared__ __align__(16) float Ssh[REP][CHLEN];
    __shared__ __align__(16) float Red[4][REP][HD];
    __shared__ __align__(16) float Kn[HD];
    __shared__ __align__(16) float Vn[HD];

    const float scale = 0.088388347648318447f;  // 1/sqrt(128)

    // stage new (post-RoPE) k,v for this (g,b)
    Kn[tid] = g_qkv[(size_t)(DIM + g * HD + tid) * NB + b];
    Vn[tid] = g_qkv[(size_t)(DIM + NKV * HD + g * HD + tid) * NB + b];

    // q: lane holds d-slice [dg*16, dg*16+16) for all 4 reps
    float qv[REP][16];
#pragma unroll
    for (int r = 0; r < REP; r++) {
        int rowBase = (g * REP + r) * HD + dg * 16;
#pragma unroll
        for (int j = 0; j < 16; j++)
            qv[r][j] = g_qkv[(size_t)(rowBase + j) * NB + b] * scale;
    }
    __syncthreads();

    const size_t strT   = (size_t)NKV * HD;                  // 1024
    const size_t baseBG = (size_t)b * TSEQ * strT + (size_t)g * HD;
    const bool special  = (c == NCHUNK - 1) && (wid == 3);   // contains t = 2047
    const int  tWarp    = c * CHLEN + wid * 64;

    // ---- scores main loop ----
    const int nIter = special ? 15 : 16;
#pragma unroll 2
    for (int i = 0; i < nIter; i++) {
        int t = tWarp + i * 4 + tq;
        const float* kp = cache_k + baseBG + (size_t)t * strT + dg * 16;
        float4 ka = *(const float4*)(kp + 0);
        float4 kb = *(const float4*)(kp + 4);
        float4 kc = *(const float4*)(kp + 8);
        float4 kd = *(const float4*)(kp + 12);
        float p[REP];
#pragma unroll
        for (int r = 0; r < REP; r++) {
            float s = qv[r][0] * ka.x;
            s = fmaf(qv[r][1], ka.y, s);  s = fmaf(qv[r][2], ka.z, s);  s = fmaf(qv[r][3], ka.w, s);
            s = fmaf(qv[r][4], kb.x, s);  s = fmaf(qv[r][5], kb.y, s);  s = fmaf(qv[r][6], kb.z, s);  s = fmaf(qv[r][7], kb.w, s);
            s = fmaf(qv[r][8], kc.x, s);  s = fmaf(qv[r][9], kc.y, s);  s = fmaf(qv[r][10], kc.z, s); s = fmaf(qv[r][11], kc.w, s);
            s = fmaf(qv[r][12], kd.x, s); s = fmaf(qv[r][13], kd.y, s); s = fmaf(qv[r][14], kd.z, s); s = fmaf(qv[r][15], kd.w, s);
            p[r] = s;
        }
#pragma unroll
        for (int off = 4; off <= 16; off <<= 1) {
#pragma unroll
            for (int r = 0; r < REP; r++) p[r] += __shfl_xor_sync(0xffffffffu, p[r], off);
        }
        if (dg == 0) {
            int tl = wid * 64 + i * 4 + tq;
#pragma unroll
            for (int r = 0; r < REP; r++) Ssh[r][tl] = p[r];
        }
    }
    // ---- scores tail (tokens 2044..2047; tq==3 uses staged new k) ----
    if (special) {
        float4 ka, kb, kc, kd;
        if (tq == 3) {
            ka = *(const float4*)&Kn[dg * 16 + 0];
            kb = *(const float4*)&Kn[dg * 16 + 4];
            kc = *(const float4*)&Kn[dg * 16 + 8];
            kd = *(const float4*)&Kn[dg * 16 + 12];
        } else {
            int t = tWarp + 60 + tq;
            const float* kp = cache_k + baseBG + (size_t)t * strT + dg * 16;
            ka = *(const float4*)(kp + 0);
            kb = *(const float4*)(kp + 4);
            kc = *(const float4*)(kp + 8);
            kd = *(const float4*)(kp + 12);
        }
        float p[REP];
#pragma unroll
        for (int r = 0; r < REP; r++) {
            float s = qv[r][0] * ka.x;
            s = fmaf(qv[r][1], ka.y, s);  s = fmaf(qv[r][2], ka.z, s);  s = fmaf(qv[r][3], ka.w, s);
            s = fmaf(qv[r][4], kb.x, s);  s = fmaf(qv[r][5], kb.y, s);  s = fmaf(qv[r][6], kb.z, s);  s = fmaf(qv[r][7], kb.w, s);
            s = fmaf(qv[r][8], kc.x, s);  s = fmaf(qv[r][9], kc.y, s);  s = fmaf(qv[r][10], kc.z, s); s = fmaf(qv[r][11], kc.w, s);
            s = fmaf(qv[r][12], kd.x, s); s = fmaf(qv[r][13], kd.y, s); s = fmaf(qv[r][14], kd.z, s); s = fmaf(qv[r][15], kd.w, s);
            p[r] = s;
        }
#pragma unroll
        for (int off = 4; off <= 16; off <<= 1) {
#pragma unroll
            for (int r = 0; r < REP; r++) p[r] += __shfl_xor_sync(0xffffffffu, p[r], off);
        }
        if (dg == 0) {
            int tl = wid * 64 + 60 + tq;
#pragma unroll
            for (int r = 0; r < REP; r++) Ssh[r][tl] = p[r];
        }
    }
    __syncthreads();

    // ---- partial softmax: warp wid handles rep r = wid ----
    {
        int r = wid;
        float v[8];
        float m = -1e30f;
#pragma unroll
        for (int j = 0; j < 8; j++) { v[j] = Ssh[r][lane + j * 32]; m = fmaxf(m, v[j]); }
#pragma unroll
        for (int off = 16; off > 0; off >>= 1) m = fmaxf(m, __shfl_xor_sync(0xffffffffu, m, off));
        float l = 0.f;
#pragma unroll
        for (int j = 0; j < 8; j++) { float e = __expf(v[j] - m); l += e; Ssh[r][lane + j * 32] = e; }
#pragma unroll
        for (int off = 16; off > 0; off >>= 1) l += __shfl_xor_sync(0xffffffffu, l, off);
        if (lane == 0) {
            int idx = ((b * NKV + g) * REP + r) * NCHUNK + c;
            g_pm[idx] = m;
            g_pl[idx] = l;
        }
    }
    __syncthreads();

    // ---- AV: warp owns 64 tokens, lane covers d = lane*4..+3 ----
    float4 a4[REP];
#pragma unroll
    for (int r = 0; r < REP; r++) { a4[r].x = a4[r].y = a4[r].z = a4[r].w = 0.f; }
    const int nAV = special ? 63 : 64;
#pragma unroll 4
    for (int i = 0; i < nAV; i++) {
        int tl = wid * 64 + i;
        int t  = c * CHLEN + tl;
        float4 v4 = *(const float4*)(cache_v + baseBG + (size_t)t * strT + lane * 4);
#pragma unroll
        for (int r = 0; r < REP; r++) {
            float p = Ssh[r][tl];
            a4[r].x = fmaf(p, v4.x, a4[r].x);
            a4[r].y = fmaf(p, v4.y, a4[r].y);
            a4[r].z = fmaf(p, v4.z, a4[r].z);
            a4[r].w = fmaf(p, v4.w, a4[r].w);
        }
    }
    if (special) {
        float4 v4 = *(const float4*)&Vn[lane * 4];
#pragma unroll
        for (int r = 0; r < REP; r++) {
            float p = Ssh[r][255];
            a4[r].x = fmaf(p, v4.x, a4[r].x);
            a4[r].y = fmaf(p, v4.y, a4[r].y);
            a4[r].z = fmaf(p, v4.z, a4[r].z);
            a4[r].w = fmaf(p, v4.w, a4[r].w);
        }
    }
#pragma unroll
    for (int r = 0; r < REP; r++) *(float4*)&Red[wid][r][lane * 4] = a4[r];
    __syncthreads();
    {
        int r = wid;
        float4 s0 = *(const float4*)&Red[0][r][lane * 4];
        float4 s1 = *(const float4*)&Red[1][r][lane * 4];
        float4 s2 = *(const float4*)&Red[2][r][lane * 4];
        float4 s3 = *(const float4*)&Red[3][r][lane * 4];
        float4 o;
        o.x = s0.x + s1.x + s2.x + s3.x;
        o.y = s0.y + s1.y + s2.y + s3.y;
        o.z = s0.z + s1.z + s2.z + s3.z;
        o.w = s0.w + s1.w + s2.w + s3.w;
        int idx = ((b * NKV + g) * REP + r) * NCHUNK + c;
        *(float4*)&g_pacc[(size_t)idx * HD + lane * 4] = o;
    }
}

// ---------------- combine 8 split-KV partials -> attT (packed layout) ----------------
__global__ void __launch_bounds__(128) k_combine() {
    int b  = blockIdx.x;
    int qh = blockIdx.y;          // qh = g*4 + r
    int base = (b * (NKV * REP) + qh) * NCHUNK;
    float m[NCHUNK];
    float M = -1e30f;
#pragma unroll
    for (int c = 0; c < NCHUNK; c++) { m[c] = g_pm[base + c]; M = fmaxf(M, m[c]); }
    float w[NCHUNK];
    float L = 0.f;
#pragma unroll
    for (int c = 0; c < NCHUNK; c++) { w[c] = __expf(m[c] - M); L = fmaf(w[c], g_pl[base + c], L); }
    float inv = 1.f / L;
    int d = threadIdx.x;
    float val = 0.f;
#pragma unroll
    for (int c = 0; c < NCHUNK; c++)
        val = fmaf(w[c], g_pacc[(size_t)(base + c) * HD + d], val);
    int row = qh * HD + d;
    g_attT[(size_t)(row >> 2) * (NB * 4) + b * 4 + (row & 3)] = val * inv;
}

// ---------------- launch ----------------
extern "C" void kernel_launch(void* const* d_in, const int* in_sizes, int n_in,
                              void* d_out, int out_size) {
    const float* x  = (const float*)d_in[0];
    const float* wq = (const float*)d_in[1];
    const float* wk = (const float*)d_in[2];
    const float* wv = (const float*)d_in[3];
    const float* wo = (const float*)d_in[4];
    const float* fc = (const float*)d_in[5];
    const float* fs = (const float*)d_in[6];
    const float* ck = (const float*)d_in[7];
    const float* cv = (const float*)d_in[8];
    float* out = (float*)d_out;

    // 1: transpose (32768 threads)
    k_transpose<<<128, 256>>>(x);
    // 2: wq (4096 rows, RoPE on all) -> g_qkv rows 0..4095
    k_gemm<4, 0, 0><<<128, 256>>>(wq, wq, 1 << 30, nullptr, 0, DIM, fc, fs);
    // 3: wk+wv fused (2048 rows, RoPE on first 1024 = k) -> g_qkv rows 4096..6143
    k_gemm<2, 0, 0><<<128, 256>>>(wk, wv, 1024, nullptr, DIM, 1024, fc, fs);
    // 4,5,6: attention split across 3 launches (chunks 0-2, 3-5, 6-7)
    k_attn<<<dim3(3, NKV, NB), 128>>>(ck, cv, 0);
    k_attn<<<dim3(3, NKV, NB), 128>>>(ck, cv, 3);
    k_attn<<<dim3(2, NKV, NB), 128>>>(ck, cv, 6);
    // 7: combine
    k_combine<<<dim3(NB, NQ), 128>>>();
    // 8: wo
    k_gemm<4, 1, 1><<<128, 256>>>(wo, wo, 1 << 30, out, 0, 0, fc, fs);
}